// round 8
// baseline (speedup 1.0000x reference)
#include <cuda_runtime.h>
#include <stdint.h>

#define NMAX 100000
#define EMAX 1600000
#define D 64

// Scratch (static device globals: allocation-free, graph-capturable).
// g_degi starts zero-initialized and is RESET in scan_kernel each launch,
// so graph replays are deterministic.
__device__ float g_xs[(size_t)NMAX * D];    // xs = (x@W) * dinv[row]
__device__ int   g_degi[NMAX];
__device__ float g_dinv[NMAX];
__device__ int   g_rowstart[NMAX + 1];
__device__ int   g_fill[NMAX];
__device__ int   g_srclist[EMAX + 32];      // slack for guarded wide reads

// ---------------------------------------------------------------------------
// K1: in-degree histogram (int atomics, spread addresses)
// ---------------------------------------------------------------------------
__global__ void deg_count_kernel(const int* __restrict__ dst, int E)
{
    int e = blockIdx.x * blockDim.x + threadIdx.x;
    if (e < E) atomicAdd(&g_degi[__ldg(&dst[e])], 1);
}

// ---------------------------------------------------------------------------
// K2: single-block exclusive prefix sum over degrees.
//   rowstart[i] = prefix; fill[i] = prefix; dinv[i] = rsqrt(deg+1);
//   degi[i] = 0 (reset for graph replay); rowstart[n] = E.
// ---------------------------------------------------------------------------
__global__ void __launch_bounds__(1024) scan_kernel(int n, int E)
{
    __shared__ int sPart[1024];
    const int t = threadIdx.x;
    const int chunk = (n + 1023) / 1024;
    const int lo = t * chunk;
    const int hi = min(n, lo + chunk);

    int sum = 0;
    for (int i = lo; i < hi; i++) sum += g_degi[i];
    sPart[t] = sum;
    __syncthreads();

    // Hillis-Steele inclusive scan on 1024 partials
    int v = sum;
    #pragma unroll
    for (int ofs = 1; ofs < 1024; ofs <<= 1) {
        int u = (t >= ofs) ? sPart[t - ofs] : 0;
        __syncthreads();
        v += u;
        sPart[t] = v;
        __syncthreads();
    }
    int running = v - sum;   // exclusive prefix for this thread's chunk

    for (int i = lo; i < hi; i++) {
        int dg = g_degi[i];
        g_rowstart[i] = running;
        g_fill[i]     = running;
        g_dinv[i]     = rsqrtf((float)(dg + 1));
        g_degi[i]     = 0;                  // reset for next replay
        running += dg;
    }
    if (t == 1023) g_rowstart[n] = E;
}

// ---------------------------------------------------------------------------
// K3: CSR fill: srclist[fill[dst]++] = src
// ---------------------------------------------------------------------------
__global__ void fill_kernel(const int* __restrict__ ei, int E)
{
    int e = blockIdx.x * blockDim.x + threadIdx.x;
    if (e < E) {
        int s = __ldg(&ei[e]);
        int d = __ldg(&ei[E + e]);
        int pos = atomicAdd(&g_fill[d], 1);
        g_srclist[pos] = s;
    }
}

// ---------------------------------------------------------------------------
// K4: xs = (x @ W) * dinv[row]
// Block: 256 threads, 64 rows per block. 4 rows x 4 cols register blocking.
// ---------------------------------------------------------------------------
__global__ void __launch_bounds__(256) gemm64_kernel(
    const float* __restrict__ x, const float* __restrict__ W, int n)
{
    __shared__ float  sX[64][65];   // padded: kills bank conflicts on column reads
    __shared__ float4 sW[64][16];   // W[k][c4] as float4

    const int t = threadIdx.x;
    const int rowBase = blockIdx.x * 64;

    {
        const float4* W4 = (const float4*)W;
        #pragma unroll
        for (int i = 0; i < 4; i++) {
            int idx = t + i * 256;
            sW[idx >> 4][idx & 15] = W4[idx];
        }
    }
    {
        #pragma unroll
        for (int i = 0; i < 4; i++) {
            int idx = t + i * 256;
            int r = idx >> 4, c4 = idx & 15;
            int row = rowBase + r;
            float4 v = make_float4(0.f, 0.f, 0.f, 0.f);
            if (row < n) v = ((const float4*)(x + (size_t)row * D))[c4];
            sX[r][c4 * 4 + 0] = v.x;
            sX[r][c4 * 4 + 1] = v.y;
            sX[r][c4 * 4 + 2] = v.z;
            sX[r][c4 * 4 + 3] = v.w;
        }
    }
    __syncthreads();

    const int c4 = t & 15;
    const int r0 = t >> 4;

    float4 acc[4];
    #pragma unroll
    for (int r = 0; r < 4; r++) acc[r] = make_float4(0.f, 0.f, 0.f, 0.f);

    #pragma unroll
    for (int k = 0; k < 64; k++) {
        float4 w = sW[k][c4];
        #pragma unroll
        for (int r = 0; r < 4; r++) {
            float xv = sX[r0 + 16 * r][k];
            acc[r].x += xv * w.x;
            acc[r].y += xv * w.y;
            acc[r].z += xv * w.z;
            acc[r].w += xv * w.w;
        }
    }

    #pragma unroll
    for (int r = 0; r < 4; r++) {
        int row = rowBase + r0 + 16 * r;
        if (row < n) {
            float di = g_dinv[row];
            float4 xs;
            xs.x = acc[r].x * di;
            xs.y = acc[r].y * di;
            xs.z = acc[r].z * di;
            xs.w = acc[r].w * di;
            ((float4*)(g_xs + (size_t)row * D))[c4] = xs;
        }
    }
}

// ---------------------------------------------------------------------------
// K5: CSR gather: out[i] = (xs[i] + sum_{s in in(i)} xs[s]) * dinv[i] + b
// 16 lanes per node (half-warp). srclist read 16-wide, shfl-broadcast.
// ---------------------------------------------------------------------------
__global__ void __launch_bounds__(256) gather_kernel(
    const float* __restrict__ b, float* __restrict__ out, int n)
{
    int t = blockIdx.x * 256 + threadIdx.x;
    int i    = t >> 4;
    int lane = t & 15;
    if (i >= n) return;

    // half-warp shfl mask
    unsigned mask = ((threadIdx.x & 31) < 16) ? 0x0000FFFFu : 0xFFFF0000u;

    int start = g_rowstart[i];
    int end   = g_rowstart[i + 1];
    float di  = g_dinv[i];

    // self message
    float4 acc = ((const float4*)(g_xs + (size_t)i * D))[lane];

    int cnt = end - start;
    for (int base = 0; base < cnt; base += 16) {
        int p = start + base + lane;
        int myidx = (p < end) ? g_srclist[p] : 0;
        int lim = cnt - base;            // >0; lanes use k < lim
        #pragma unroll
        for (int k = 0; k < 16; k++) {
            int s = __shfl_sync(mask, myidx, k, 16);
            if (k < lim) {
                float4 v = ((const float4*)(g_xs + (size_t)s * D))[lane];
                acc.x += v.x;
                acc.y += v.y;
                acc.z += v.z;
                acc.w += v.w;
            }
        }
    }

    float4 bb = ((const float4*)b)[lane];
    float4 o;
    o.x = acc.x * di + bb.x;
    o.y = acc.y * di + bb.y;
    o.z = acc.z * di + bb.z;
    o.w = acc.w * di + bb.w;
    ((float4*)(out + (size_t)i * D))[lane] = o;
}

// ---------------------------------------------------------------------------
// Launch
// Inputs (metadata order): x [n*64] f32, edge_index [2*E] int32, W [64*64] f32,
//                          b [64] f32. Output: [n*64] f32.
// 5 launches: deg_count, scan, fill, gemm, gather.
// ---------------------------------------------------------------------------
extern "C" void kernel_launch(void* const* d_in, const int* in_sizes, int n_in,
                              void* d_out, int out_size)
{
    const float* x  = (const float*)d_in[0];
    const int*   ei = (const int*)d_in[1];
    const float* W  = (const float*)d_in[2];
    const float* b  = (const float*)d_in[3];
    float*       out = (float*)d_out;

    const int n = in_sizes[0] / D;       // 100000
    const int E = in_sizes[1] / 2;       // 1600000

    deg_count_kernel<<<(E + 255) / 256, 256>>>(ei + E, E);
    scan_kernel<<<1, 1024>>>(n, E);
    fill_kernel<<<(E + 255) / 256, 256>>>(ei, E);
    gemm64_kernel<<<(n + 63) / 64, 256>>>(x, W, n);
    {
        int total = n * 16;
        gather_kernel<<<(total + 255) / 256, 256>>>(b, out, n);
    }
}

// round 9
// speedup vs baseline: 2.9859x; 2.9859x over previous
#include <cuda_runtime.h>
#include <stdint.h>

#define NMAX 100000
#define EMAX 1600000
#define D 64

// Scratch (static device globals: allocation-free, graph-capturable).
// g_deg starts zero-initialized and is RESET by dinv_kernel each launch,
// so graph replays are deterministic.
__device__ float g_xs[(size_t)NMAX * D];   // xs = (x@W) * dinv[row]
__device__ float g_deg[NMAX];
__device__ float g_dinv[NMAX];

// ---------------------------------------------------------------------------
// K1: deg[dst[e]] += 1 (deg starts 0; self-loop folded into rsqrt below)
// ---------------------------------------------------------------------------
__global__ void deg_count_kernel(const int* __restrict__ dst, int E)
{
    int e = blockIdx.x * blockDim.x + threadIdx.x;
    if (e < E) atomicAdd(&g_deg[__ldg(&dst[e])], 1.0f);
}

// ---------------------------------------------------------------------------
// K2: dinv[i] = rsqrt(deg[i]+1); deg[i] = 0 (reset for graph replay)
// ---------------------------------------------------------------------------
__global__ void dinv_kernel(int n)
{
    int i = blockIdx.x * blockDim.x + threadIdx.x;
    if (i < n) {
        g_dinv[i] = rsqrtf(g_deg[i] + 1.0f);
        g_deg[i] = 0.0f;
    }
}

// ---------------------------------------------------------------------------
// K3: xs = (x@W) * dinv[row];  out[row] = xs * dinv[row] + b (self-loop+bias)
// 256 threads, 64 rows/block, 4 rows x 4 cols register blocking.
// k-loop unrolled by 4 with LDS.128 x-row reads (broadcast, conflict-free).
// ---------------------------------------------------------------------------
__global__ void __launch_bounds__(256) gemm64_kernel(
    const float* __restrict__ x, const float* __restrict__ W,
    const float* __restrict__ b, float* __restrict__ out, int n)
{
    __shared__ float  sX[64][68];   // 68: 16B-aligned rows (272B), no col reads
    __shared__ float4 sW[64][16];

    const int t = threadIdx.x;
    const int rowBase = blockIdx.x * 64;

    {
        const float4* W4 = (const float4*)W;
        #pragma unroll
        for (int i = 0; i < 4; i++) {
            int idx = t + i * 256;
            sW[idx >> 4][idx & 15] = W4[idx];
        }
    }
    {
        #pragma unroll
        for (int i = 0; i < 4; i++) {
            int idx = t + i * 256;
            int r = idx >> 4, c4 = idx & 15;
            int row = rowBase + r;
            float4 v = make_float4(0.f, 0.f, 0.f, 0.f);
            if (row < n) v = ((const float4*)(x + (size_t)row * D))[c4];
            *(float4*)&sX[r][c4 * 4] = v;
        }
    }
    __syncthreads();

    const int c4 = t & 15;   // column float4 group
    const int r0 = t >> 4;   // rows r0, r0+16, r0+32, r0+48

    float4 acc[4];
    #pragma unroll
    for (int r = 0; r < 4; r++) acc[r] = make_float4(0.f, 0.f, 0.f, 0.f);

    #pragma unroll
    for (int k = 0; k < 64; k += 4) {
        float4 w0 = sW[k + 0][c4];
        float4 w1 = sW[k + 1][c4];
        float4 w2 = sW[k + 2][c4];
        float4 w3 = sW[k + 3][c4];
        #pragma unroll
        for (int r = 0; r < 4; r++) {
            float4 xv = *(const float4*)&sX[r0 + 16 * r][k];  // broadcast LDS.128
            acc[r].x += xv.x * w0.x + xv.y * w1.x + xv.z * w2.x + xv.w * w3.x;
            acc[r].y += xv.x * w0.y + xv.y * w1.y + xv.z * w2.y + xv.w * w3.y;
            acc[r].z += xv.x * w0.z + xv.y * w1.z + xv.z * w2.z + xv.w * w3.z;
            acc[r].w += xv.x * w0.w + xv.y * w1.w + xv.z * w2.w + xv.w * w3.w;
        }
    }

    float4 bb = ((const float4*)b)[c4];

    #pragma unroll
    for (int r = 0; r < 4; r++) {
        int row = rowBase + r0 + 16 * r;
        if (row < n) {
            float di = g_dinv[row];
            float4 xs;
            xs.x = acc[r].x * di;
            xs.y = acc[r].y * di;
            xs.z = acc[r].z * di;
            xs.w = acc[r].w * di;
            ((float4*)(g_xs + (size_t)row * D))[c4] = xs;
            float4 o;
            o.x = xs.x * di + bb.x;
            o.y = xs.y * di + bb.y;
            o.z = xs.z * di + bb.z;
            o.w = xs.w * di + bb.w;
            ((float4*)(out + (size_t)row * D))[c4] = o;
        }
    }
}

// ---------------------------------------------------------------------------
// K4: edge scatter: out[dst] += xs[src] * dinv[dst]
// 16 lanes per edge, 2 edges per thread (e and e+Ehalf) for MLP.
// One red.global.add.v4.f32 (16B) per edge per lane.
// ---------------------------------------------------------------------------
__device__ __forceinline__ void red_add_v4(float* dp, float a, float b, float c, float d)
{
#if !defined(__CUDA_ARCH__) || __CUDA_ARCH__ >= 900
    asm volatile(
        "red.global.add.v4.f32 [%0], {%1, %2, %3, %4};"
        :: "l"(dp), "f"(a), "f"(b), "f"(c), "f"(d)
        : "memory");
#else
    atomicAdd(dp + 0, a);
    atomicAdd(dp + 1, b);
    atomicAdd(dp + 2, c);
    atomicAdd(dp + 3, d);
#endif
}

__global__ void __launch_bounds__(256) scatter_kernel(
    const int* __restrict__ ei, float* __restrict__ out, int E, int Ehalf)
{
    unsigned int t = blockIdx.x * 256u + threadIdx.x;
    int g    = (int)(t >> 4);
    int lane = (int)(t & 15);
    if (g >= Ehalf) return;

    int e0 = g;
    int e1 = g + Ehalf;
    bool has1 = (e1 < E);

    // Issue all independent loads up front (MLP)
    int s0 = __ldg(&ei[e0]);
    int d0 = __ldg(&ei[E + e0]);
    int s1 = has1 ? __ldg(&ei[e1]) : 0;
    int d1 = has1 ? __ldg(&ei[E + e1]) : 0;

    float c0 = g_dinv[d0];
    float c1 = has1 ? g_dinv[d1] : 0.0f;

    float4 v0 = ((const float4*)(g_xs + (size_t)s0 * D))[lane];
    float4 v1 = has1 ? ((const float4*)(g_xs + (size_t)s1 * D))[lane]
                     : make_float4(0.f, 0.f, 0.f, 0.f);

    float* dp0 = out + (size_t)d0 * D + lane * 4;
    red_add_v4(dp0, v0.x * c0, v0.y * c0, v0.z * c0, v0.w * c0);

    if (has1) {
        float* dp1 = out + (size_t)d1 * D + lane * 4;
        red_add_v4(dp1, v1.x * c1, v1.y * c1, v1.z * c1, v1.w * c1);
    }
}

// ---------------------------------------------------------------------------
// Launch
// Inputs (metadata order): x [n*64] f32, edge_index [2*E] int32, W [64*64] f32,
//                          b [64] f32. Output: [n*64] f32.
// 4 launches: deg_count, dinv, gemm(+epilogue), scatter.
// ---------------------------------------------------------------------------
extern "C" void kernel_launch(void* const* d_in, const int* in_sizes, int n_in,
                              void* d_out, int out_size)
{
    const float* x  = (const float*)d_in[0];
    const int*   ei = (const int*)d_in[1];
    const float* W  = (const float*)d_in[2];
    const float* b  = (const float*)d_in[3];
    float*       out = (float*)d_out;

    const int n = in_sizes[0] / D;       // 100000
    const int E = in_sizes[1] / 2;       // 1600000
    const int Ehalf = (E + 1) / 2;

    deg_count_kernel<<<(E + 255) / 256, 256>>>(ei + E, E);
    dinv_kernel<<<(n + 255) / 256, 256>>>(n);
    gemm64_kernel<<<(n + 63) / 64, 256>>>(x, W, b, out, n);
    {
        long long total = (long long)Ehalf * 16;
        int blocks = (int)((total + 255) / 256);
        scatter_kernel<<<blocks, 256>>>(ei, out, E, Ehalf);
    }
}

// round 10
// speedup vs baseline: 3.1939x; 1.0696x over previous
#include <cuda_runtime.h>
#include <cuda_fp16.h>
#include <stdint.h>

#define NMAX 100000
#define EMAX 1600000
#define D 64

// Scratch (static device globals: allocation-free, graph-capturable).
// g_deg starts zero-initialized and is RESET by dinv_kernel each launch,
// so graph replays are deterministic.
__device__ __half g_xsh[(size_t)NMAX * D];  // xs = (x@W)*dinv[row], fp16
__device__ float  g_deg[NMAX];
__device__ float  g_dinv[NMAX];

// ---------------------------------------------------------------------------
// K1: deg[dst[e]] += 1 (deg starts 0; self-loop folded into rsqrt below)
// 2 edges per thread via int2.
// ---------------------------------------------------------------------------
__global__ void deg_count_kernel(const int* __restrict__ dst, int E)
{
    int g = blockIdx.x * blockDim.x + threadIdx.x;
    int e0 = 2 * g;
    if (e0 + 1 < E) {
        int2 dd = *(const int2*)&dst[e0];
        atomicAdd(&g_deg[dd.x], 1.0f);
        atomicAdd(&g_deg[dd.y], 1.0f);
    } else if (e0 < E) {
        atomicAdd(&g_deg[__ldg(&dst[e0])], 1.0f);
    }
}

// ---------------------------------------------------------------------------
// K2: dinv[i] = rsqrt(deg[i]+1); deg[i] = 0 (reset for graph replay)
// ---------------------------------------------------------------------------
__global__ void dinv_kernel(int n)
{
    int i = blockIdx.x * blockDim.x + threadIdx.x;
    if (i < n) {
        g_dinv[i] = rsqrtf(g_deg[i] + 1.0f);
        g_deg[i] = 0.0f;
    }
}

// ---------------------------------------------------------------------------
// K3: xs = (x@W)*dinv[row] -> fp16 g_xsh;  out[row] = xs*dinv + b (fp32 path)
// 256 threads, 64 rows/block, 4 rows x 4 cols register blocking.
// k-loop unrolled by 4 with LDS.128 broadcast x-row reads.
// ---------------------------------------------------------------------------
__global__ void __launch_bounds__(256) gemm64_kernel(
    const float* __restrict__ x, const float* __restrict__ W,
    const float* __restrict__ b, float* __restrict__ out, int n)
{
    __shared__ float  sX[64][68];   // 68: keeps 16B alignment of row starts
    __shared__ float4 sW[64][16];

    const int t = threadIdx.x;
    const int rowBase = blockIdx.x * 64;

    {
        const float4* W4 = (const float4*)W;
        #pragma unroll
        for (int i = 0; i < 4; i++) {
            int idx = t + i * 256;
            sW[idx >> 4][idx & 15] = W4[idx];
        }
    }
    {
        #pragma unroll
        for (int i = 0; i < 4; i++) {
            int idx = t + i * 256;
            int r = idx >> 4, c4 = idx & 15;
            int row = rowBase + r;
            float4 v = make_float4(0.f, 0.f, 0.f, 0.f);
            if (row < n) v = ((const float4*)(x + (size_t)row * D))[c4];
            *(float4*)&sX[r][c4 * 4] = v;
        }
    }
    __syncthreads();

    const int c4 = t & 15;
    const int r0 = t >> 4;

    float4 acc[4];
    #pragma unroll
    for (int r = 0; r < 4; r++) acc[r] = make_float4(0.f, 0.f, 0.f, 0.f);

    #pragma unroll
    for (int k = 0; k < 64; k += 4) {
        float4 w0 = sW[k + 0][c4];
        float4 w1 = sW[k + 1][c4];
        float4 w2 = sW[k + 2][c4];
        float4 w3 = sW[k + 3][c4];
        #pragma unroll
        for (int r = 0; r < 4; r++) {
            float4 xv = *(const float4*)&sX[r0 + 16 * r][k];  // LDS.128 broadcast
            acc[r].x += xv.x * w0.x + xv.y * w1.x + xv.z * w2.x + xv.w * w3.x;
            acc[r].y += xv.x * w0.y + xv.y * w1.y + xv.z * w2.y + xv.w * w3.y;
            acc[r].z += xv.x * w0.z + xv.y * w1.z + xv.z * w2.z + xv.w * w3.z;
            acc[r].w += xv.x * w0.w + xv.y * w1.w + xv.z * w2.w + xv.w * w3.w;
        }
    }

    float4 bb = ((const float4*)b)[c4];

    #pragma unroll
    for (int r = 0; r < 4; r++) {
        int row = rowBase + r0 + 16 * r;
        if (row < n) {
            float di = g_dinv[row];
            float4 xs;
            xs.x = acc[r].x * di;
            xs.y = acc[r].y * di;
            xs.z = acc[r].z * di;
            xs.w = acc[r].w * di;
            // fp16 message row (scatter source)
            __half2* hp = (__half2*)(g_xsh + (size_t)row * D);
            hp[c4 * 2 + 0] = __floats2half2_rn(xs.x, xs.y);
            hp[c4 * 2 + 1] = __floats2half2_rn(xs.z, xs.w);
            // self-loop + bias in full fp32
            float4 o;
            o.x = xs.x * di + bb.x;
            o.y = xs.y * di + bb.y;
            o.z = xs.z * di + bb.z;
            o.w = xs.w * di + bb.w;
            ((float4*)(out + (size_t)row * D))[c4] = o;
        }
    }
}

// ---------------------------------------------------------------------------
// K4: edge scatter: out[dst] += float(xsh[src]) * dinv[dst]
// 16 lanes per edge, 4 consecutive edges per thread-group (int4 idx loads,
// MLP=4 on gathers). Per edge per lane: 8B fp16 load + 16B red.v4.f32.
// ---------------------------------------------------------------------------
__device__ __forceinline__ void red_add_v4(float* dp, float a, float b, float c, float d)
{
#if !defined(__CUDA_ARCH__) || __CUDA_ARCH__ >= 900
    asm volatile(
        "red.global.add.v4.f32 [%0], {%1, %2, %3, %4};"
        :: "l"(dp), "f"(a), "f"(b), "f"(c), "f"(d)
        : "memory");
#else
    atomicAdd(dp + 0, a);
    atomicAdd(dp + 1, b);
    atomicAdd(dp + 2, c);
    atomicAdd(dp + 3, d);
#endif
}

__device__ __forceinline__ void scatter_one(int s, int d, int lane,
                                            float* __restrict__ out)
{
    float c = g_dinv[d];
    // 4 halves (8B) per lane
    uint2 raw = *(const uint2*)(g_xsh + (size_t)s * D + lane * 4);
    __half2 h0 = *reinterpret_cast<__half2*>(&raw.x);
    __half2 h1 = *reinterpret_cast<__half2*>(&raw.y);
    float2 f0 = __half22float2(h0);
    float2 f1 = __half22float2(h1);
    float* dp = out + (size_t)d * D + lane * 4;
    red_add_v4(dp, f0.x * c, f0.y * c, f1.x * c, f1.y * c);
}

__global__ void __launch_bounds__(256) scatter_kernel(
    const int* __restrict__ ei, float* __restrict__ out, int E)
{
    unsigned int t = blockIdx.x * 256u + threadIdx.x;
    int g    = (int)(t >> 4);
    int lane = (int)(t & 15);
    int nquad = E >> 2;

    if (g < nquad) {
        int e = 4 * g;
        int4 ss = *(const int4*)&ei[e];
        int4 dd = *(const int4*)&ei[E + e];

        // load all dinv + gathers up front for MLP
        float c0 = g_dinv[dd.x], c1 = g_dinv[dd.y];
        float c2 = g_dinv[dd.z], c3 = g_dinv[dd.w];
        uint2 r0 = *(const uint2*)(g_xsh + (size_t)ss.x * D + lane * 4);
        uint2 r1 = *(const uint2*)(g_xsh + (size_t)ss.y * D + lane * 4);
        uint2 r2 = *(const uint2*)(g_xsh + (size_t)ss.z * D + lane * 4);
        uint2 r3 = *(const uint2*)(g_xsh + (size_t)ss.w * D + lane * 4);

        {
            float2 a = __half22float2(*reinterpret_cast<__half2*>(&r0.x));
            float2 b = __half22float2(*reinterpret_cast<__half2*>(&r0.y));
            red_add_v4(out + (size_t)dd.x * D + lane * 4,
                       a.x * c0, a.y * c0, b.x * c0, b.y * c0);
        }
        {
            float2 a = __half22float2(*reinterpret_cast<__half2*>(&r1.x));
            float2 b = __half22float2(*reinterpret_cast<__half2*>(&r1.y));
            red_add_v4(out + (size_t)dd.y * D + lane * 4,
                       a.x * c1, a.y * c1, b.x * c1, b.y * c1);
        }
        {
            float2 a = __half22float2(*reinterpret_cast<__half2*>(&r2.x));
            float2 b = __half22float2(*reinterpret_cast<__half2*>(&r2.y));
            red_add_v4(out + (size_t)dd.z * D + lane * 4,
                       a.x * c2, a.y * c2, b.x * c2, b.y * c2);
        }
        {
            float2 a = __half22float2(*reinterpret_cast<__half2*>(&r3.x));
            float2 b = __half22float2(*reinterpret_cast<__half2*>(&r3.y));
            red_add_v4(out + (size_t)dd.w * D + lane * 4,
                       a.x * c3, a.y * c3, b.x * c3, b.y * c3);
        }
    } else if (g == nquad) {
        // tail edges (E not divisible by 4): handled by one group serially
        for (int e = 4 * nquad; e < E; e++) {
            int s = __ldg(&ei[e]);
            int d = __ldg(&ei[E + e]);
            scatter_one(s, d, lane, out);
        }
    }
}

// ---------------------------------------------------------------------------
// Launch
// Inputs (metadata order): x [n*64] f32, edge_index [2*E] int32, W [64*64] f32,
//                          b [64] f32. Output: [n*64] f32.
// 4 launches: deg_count, dinv, gemm(+epilogue), scatter.
// ---------------------------------------------------------------------------
extern "C" void kernel_launch(void* const* d_in, const int* in_sizes, int n_in,
                              void* d_out, int out_size)
{
    const float* x  = (const float*)d_in[0];
    const int*   ei = (const int*)d_in[1];
    const float* W  = (const float*)d_in[2];
    const float* b  = (const float*)d_in[3];
    float*       out = (float*)d_out;

    const int n = in_sizes[0] / D;       // 100000
    const int E = in_sizes[1] / 2;       // 1600000

    {
        int pairs = (E + 1) / 2;
        deg_count_kernel<<<(pairs + 255) / 256, 256>>>(ei + E, E);
    }
    dinv_kernel<<<(n + 255) / 256, 256>>>(n);
    gemm64_kernel<<<(n + 63) / 64, 256>>>(x, W, b, out, n);
    {
        int groups = (E >> 2) + 1;           // quads + tail group
        long long total = (long long)groups * 16;
        int blocks = (int)((total + 255) / 256);
        scatter_kernel<<<blocks, 256>>>(ei, out, E);
    }
}